// round 13
// baseline (speedup 1.0000x reference)
#include <cuda_runtime.h>
#include <cuda_fp16.h>
#include <mma.h>
#include <cstddef>
#include <cstdint>

using namespace nvcuda;

#define N_NODES   50000
#define N_GRAPHS  128
#define IN_C      128
#define HID_C     128
#define OUT_C     64
#define E_MAX     700000

// ---------------- device scratch (no allocations allowed) ----------------
__device__ int    g_degi[N_NODES];
__device__ int    g_cur [N_NODES];                   // CSR fill cursors
__device__ int2   g_csr_sd[E_MAX];                   // (src,dst) sorted by dst
__device__ float  g_dinv[N_NODES];
__device__ __half g_g1h [(size_t)N_NODES * HID_C];   // fp16 messages L1
__device__ __half g_acc1[(size_t)N_NODES * HID_C];   // fp16 scatter accumulator L1
__device__ __half g_g2h [(size_t)N_NODES * OUT_C];   // fp16 messages L2
__device__ __half g_acc2[(size_t)N_NODES * OUT_C];   // fp16 scatter accumulator L2
__device__ float  g_gsum[N_GRAPHS * OUT_C];
__device__ float  g_gcnt[N_GRAPHS];

__device__ __forceinline__ void red_add_v4(float* p, float4 v) {
    asm volatile("red.global.add.v4.f32 [%0], {%1, %2, %3, %4};"
                 :: "l"(p), "f"(v.x), "f"(v.y), "f"(v.z), "f"(v.w)
                 : "memory");
}
// 8 halfs per op (16B) — sm_90+
__device__ __forceinline__ void red_add_v4h(__half* p, uint4 v) {
    asm volatile("red.global.add.noftz.v4.f16x2 [%0], {%1, %2, %3, %4};"
                 :: "l"(p), "r"(v.x), "r"(v.y), "r"(v.z), "r"(v.w)
                 : "memory");
}
__device__ __forceinline__ void h2x4_add(uint4& a, uint4 b) {
    __half2* pa = (__half2*)&a;
    const __half2* pb = (const __half2*)&b;
    pa[0] = __hadd2(pa[0], pb[0]);
    pa[1] = __hadd2(pa[1], pb[1]);
    pa[2] = __hadd2(pa[2], pb[2]);
    pa[3] = __hadd2(pa[3], pb[3]);
}
__device__ __forceinline__ uint4 f8_to_h8(float4 a, float4 b) {
    __half2 h0 = __floats2half2_rn(a.x, a.y);
    __half2 h1 = __floats2half2_rn(a.z, a.w);
    __half2 h2 = __floats2half2_rn(b.x, b.y);
    __half2 h3 = __floats2half2_rn(b.z, b.w);
    uint4 u;
    u.x = *reinterpret_cast<unsigned*>(&h0);
    u.y = *reinterpret_cast<unsigned*>(&h1);
    u.z = *reinterpret_cast<unsigned*>(&h2);
    u.w = *reinterpret_cast<unsigned*>(&h3);
    return u;
}

// ---------------- degree (by dst) ----------------
__global__ void deg_kernel(const int* __restrict__ dst, int E) {
    int e = blockIdx.x * blockDim.x + threadIdx.x;
    if (e < E) atomicAdd(&g_degi[dst[e]], 1);
}

// ---------------- exclusive scan -> cursors; dinv (1 block, 1024 thr) ----------------
__global__ void scan_kernel(int N) {
    __shared__ int ssum[1024];
    const int tid = threadIdx.x;
    const int C   = (N + 1023) / 1024;
    const int lo  = tid * C;
    const int hi  = min(lo + C, N);

    int s = 0;
    for (int i = lo; i < hi; i++) s += g_degi[i];
    ssum[tid] = s;
    __syncthreads();
    for (int off = 1; off < 1024; off <<= 1) {
        int v = (tid >= off) ? ssum[tid - off] : 0;
        __syncthreads();
        ssum[tid] += v;
        __syncthreads();
    }
    int running = ssum[tid] - s;   // exclusive base
    for (int i = lo; i < hi; i++) {
        g_cur[i] = running;
        int d = g_degi[i];
        g_dinv[i] = rsqrtf((float)(1 + d));   // +1 self-loop
        running += d;
    }
}

// ---------------- fill: dst-sorted (src,dst) pairs ----------------
__global__ void fill_kernel(const int* __restrict__ src,
                            const int* __restrict__ dst,
                            int E) {
    int e = blockIdx.x * blockDim.x + threadIdx.x;
    if (e < E) {
        int d = dst[e];
        int pos = atomicAdd(&g_cur[d], 1);
        g_csr_sd[pos] = make_int2(src[e], d);
    }
}

// ---------------- fp16 HMMA GEMM: C16 = dinv ⊙ (A[M,128] @ B[128,LD]) ----------------
// BM=128, 256 threads = 8 warps as 4(m) x 2(n).
// FUSE_IN: A row = relu(dinv*(acc1+g1h)+bias)  (layer-2 input, fp16 sources).
template<int LD, bool FUSE_IN>
__global__ void __launch_bounds__(256)
hgemm_kernel(const float* __restrict__ A,
             const float* __restrict__ bias,
             const float* __restrict__ B,
             __half* __restrict__ C16, int M) {
    extern __shared__ __half sm[];
    constexpr int LDA = 136;
    constexpr int LDB = LD + 8;
    constexpr int NT  = LD / 32;
    __half* As = sm;
    __half* Bs = sm + 128 * LDA;

    const int tid    = threadIdx.x;
    const int wid    = tid >> 5;
    const int lane   = tid & 31;
    const int warp_m = wid >> 1;
    const int warp_n = wid & 1;
    const int row0   = blockIdx.x * 128;

#pragma unroll
    for (int it = 0; it < 8; it++) {
        int chunk = tid + it * 256;
        int r  = chunk >> 4;
        int c8 = chunk & 15;
        int grow = row0 + r;
        uint4 u;
        if (grow < M) {
            if (FUSE_IN) {
                float dv = g_dinv[grow];
                uint4 au = ((const uint4*)(g_acc1 + (size_t)grow * 128))[c8];
                uint4 gu = ((const uint4*)(g_g1h  + (size_t)grow * 128))[c8];
                float4 bv0 = *(const float4*)(bias + c8 * 8);
                float4 bv1 = *(const float4*)(bias + c8 * 8 + 4);
                const __half2* ah = (const __half2*)&au;
                const __half2* gh = (const __half2*)&gu;
                float4 lo, hi;
                float2 t0 = __half22float2(ah[0]), s0 = __half22float2(gh[0]);
                float2 t1 = __half22float2(ah[1]), s1 = __half22float2(gh[1]);
                float2 t2 = __half22float2(ah[2]), s2 = __half22float2(gh[2]);
                float2 t3 = __half22float2(ah[3]), s3 = __half22float2(gh[3]);
                lo.x = fmaxf(dv * (t0.x + s0.x) + bv0.x, 0.f);
                lo.y = fmaxf(dv * (t0.y + s0.y) + bv0.y, 0.f);
                lo.z = fmaxf(dv * (t1.x + s1.x) + bv0.z, 0.f);
                lo.w = fmaxf(dv * (t1.y + s1.y) + bv0.w, 0.f);
                hi.x = fmaxf(dv * (t2.x + s2.x) + bv1.x, 0.f);
                hi.y = fmaxf(dv * (t2.y + s2.y) + bv1.y, 0.f);
                hi.z = fmaxf(dv * (t3.x + s3.x) + bv1.z, 0.f);
                hi.w = fmaxf(dv * (t3.y + s3.y) + bv1.w, 0.f);
                u = f8_to_h8(lo, hi);
            } else {
                float4 lo = *(const float4*)(A + (size_t)grow * 128 + c8 * 8);
                float4 hi = *(const float4*)(A + (size_t)grow * 128 + c8 * 8 + 4);
                u = f8_to_h8(lo, hi);
            }
        } else {
            u = make_uint4(0, 0, 0, 0);
        }
        *(uint4*)(As + r * LDA + c8 * 8) = u;
    }
    constexpr int BCH = 128 * LD / 8 / 256;
#pragma unroll
    for (int it = 0; it < BCH; it++) {
        int chunk = tid + it * 256;
        int r  = chunk / (LD / 8);
        int c8 = chunk % (LD / 8);
        float4 lo = *(const float4*)(B + (size_t)r * LD + c8 * 8);
        float4 hi = *(const float4*)(B + (size_t)r * LD + c8 * 8 + 4);
        *(uint4*)(Bs + r * LDB + c8 * 8) = f8_to_h8(lo, hi);
    }
    __syncthreads();

    wmma::fragment<wmma::accumulator, 16, 16, 16, float> acc[2][NT];
#pragma unroll
    for (int i = 0; i < 2; i++)
#pragma unroll
        for (int nt = 0; nt < NT; nt++) wmma::fill_fragment(acc[i][nt], 0.f);

#pragma unroll
    for (int k = 0; k < 8; k++) {
        wmma::fragment<wmma::matrix_a, 16, 16, 16, __half, wmma::row_major> a0, a1;
        wmma::load_matrix_sync(a0, As + (warp_m * 32 +  0) * LDA + k * 16, LDA);
        wmma::load_matrix_sync(a1, As + (warp_m * 32 + 16) * LDA + k * 16, LDA);
#pragma unroll
        for (int nt = 0; nt < NT; nt++) {
            wmma::fragment<wmma::matrix_b, 16, 16, 16, __half, wmma::row_major> b;
            wmma::load_matrix_sync(b, Bs + (k * 16) * LDB + warp_n * (LD / 2) + nt * 16, LDB);
            wmma::mma_sync(acc[0][nt], a0, b, acc[0][nt]);
            wmma::mma_sync(acc[1][nt], a1, b, acc[1][nt]);
        }
    }
    __syncthreads();

    float* wbuf = (float*)(sm) + wid * 256;    // ldm=16 (16B multiple — WMMA contract)
#pragma unroll
    for (int i = 0; i < 2; i++) {
#pragma unroll
        for (int nt = 0; nt < NT; nt++) {
            wmma::store_matrix_sync(wbuf, acc[i][nt], 16, wmma::mem_row_major);
            __syncwarp();
            int r  = lane >> 1;
            int c8 = (lane & 1) * 8;
            int grow = row0 + warp_m * 32 + i * 16 + r;
            if (grow < M) {
                float d = g_dinv[grow];
                const float* p = wbuf + r * 16 + c8;
                float4 lo = make_float4(d * p[0], d * p[1], d * p[2], d * p[3]);
                float4 hi = make_float4(d * p[4], d * p[5], d * p[6], d * p[7]);
                int col = warp_n * (LD / 2) + nt * 16 + c8;
                *(uint4*)(C16 + (size_t)grow * LD + col) = f8_to_h8(lo, hi);
            }
            __syncwarp();
        }
    }
}

// ---------------- scatter 1 (dst-sorted runs of 8, register combine) ----------------
// 16-lane group handles 8 consecutive sorted edges; row = 128 halfs = 16 uint4.
__global__ void __launch_bounds__(256)
scatter1s_kernel(int E) {
    int t = blockIdx.x * blockDim.x + threadIdx.x;
    int grp  = t >> 4;
    int lane = t & 15;
    int e0 = grp * 8;
    if (e0 >= E) return;

    const uint4* base = (const uint4*)g_g1h;   // 16 uint4 per row
    int2 sd[8];
#pragma unroll
    for (int j = 0; j < 8; j++)
        sd[j] = (e0 + j < E) ? g_csr_sd[e0 + j] : make_int2(0, -1);
    uint4 v[8];
#pragma unroll
    for (int j = 0; j < 8; j++)
        v[j] = (sd[j].y >= 0) ? base[(size_t)sd[j].x * 16 + lane]
                              : make_uint4(0, 0, 0, 0);

    uint4 acc = v[0];
    int   cur = sd[0].y;      // e0 < E, so valid
#pragma unroll
    for (int j = 1; j < 8; j++) {
        if (sd[j].y == cur) {
            h2x4_add(acc, v[j]);
        } else {
            if (cur >= 0) red_add_v4h(g_acc1 + (size_t)cur * HID_C + lane * 8, acc);
            cur = sd[j].y;
            acc = v[j];
        }
    }
    if (cur >= 0) red_add_v4h(g_acc1 + (size_t)cur * HID_C + lane * 8, acc);
}

// ---------------- scatter 2 (dst-sorted runs of 8) ----------------
// 8-lane group handles 8 consecutive sorted edges; row = 64 halfs = 8 uint4.
__global__ void __launch_bounds__(256)
scatter2s_kernel(int E) {
    int t = blockIdx.x * blockDim.x + threadIdx.x;
    int grp  = t >> 3;
    int lane = t & 7;
    int e0 = grp * 8;
    if (e0 >= E) return;

    const uint4* base = (const uint4*)g_g2h;   // 8 uint4 per row
    int2 sd[8];
#pragma unroll
    for (int j = 0; j < 8; j++)
        sd[j] = (e0 + j < E) ? g_csr_sd[e0 + j] : make_int2(0, -1);
    uint4 v[8];
#pragma unroll
    for (int j = 0; j < 8; j++)
        v[j] = (sd[j].y >= 0) ? base[(size_t)sd[j].x * 8 + lane]
                              : make_uint4(0, 0, 0, 0);

    uint4 acc = v[0];
    int   cur = sd[0].y;
#pragma unroll
    for (int j = 1; j < 8; j++) {
        if (sd[j].y == cur) {
            h2x4_add(acc, v[j]);
        } else {
            if (cur >= 0) red_add_v4h(g_acc2 + (size_t)cur * OUT_C + lane * 8, acc);
            cur = sd[j].y;
            acc = v[j];
        }
    }
    if (cur >= 0) red_add_v4h(g_acc2 + (size_t)cur * OUT_C + lane * 8, acc);
}

// ---------------- pool: out2 = dinv*(acc2+g2h)+b2; RED into graph sums ----------------
__global__ void pool_kernel(const int* __restrict__ batch,
                            const float* __restrict__ b2,
                            int N) {
    int t = blockIdx.x * blockDim.x + threadIdx.x;
    int node = t >> 4;
    int lane = t & 15;
    if (node >= N) return;
    int b = batch[node];
    float dv = g_dinv[node];
    uint2 au = ((const uint2*)(g_acc2 + (size_t)node * OUT_C))[lane];
    uint2 gu = ((const uint2*)(g_g2h  + (size_t)node * OUT_C))[lane];
    __half2 ah0 = *reinterpret_cast<__half2*>(&au.x);
    __half2 ah1 = *reinterpret_cast<__half2*>(&au.y);
    __half2 gh0 = *reinterpret_cast<__half2*>(&gu.x);
    __half2 gh1 = *reinterpret_cast<__half2*>(&gu.y);
    float2 a0 = __half22float2(ah0), a1 = __half22float2(ah1);
    float2 g0 = __half22float2(gh0), g1 = __half22float2(gh1);
    float4 bv = *(const float4*)(b2 + lane * 4);
    float4 r;
    r.x = dv * (a0.x + g0.x) + bv.x;
    r.y = dv * (a0.y + g0.y) + bv.y;
    r.z = dv * (a1.x + g1.x) + bv.z;
    r.w = dv * (a1.y + g1.y) + bv.w;
    red_add_v4(g_gsum + b * OUT_C + lane * 4, r);
    if (lane == 0) atomicAdd(&g_gcnt[b], 1.0f);
}

__global__ void divide_kernel(float* __restrict__ out, int G) {
    int i = blockIdx.x * blockDim.x + threadIdx.x;
    if (i < G * OUT_C) {
        float c = g_gcnt[i / OUT_C];
        out[i] = g_gsum[i] / fmaxf(c, 1.0f);
    }
}

// ---------------- launch ----------------
extern "C" void kernel_launch(void* const* d_in, const int* in_sizes, int n_in,
                              void* d_out, int out_size) {
    const float* x   = (const float*)d_in[0];
    const float* W1  = (const float*)d_in[1];
    const float* b1  = (const float*)d_in[2];
    const float* W2  = (const float*)d_in[3];
    const float* b2  = (const float*)d_in[4];
    const int*   ei  = (const int*)d_in[5];   // int32
    const int*   bat = (const int*)d_in[6];

    const int N = in_sizes[0] / IN_C;      // 50000
    const int E = in_sizes[5] / 2;         // 625000
    const int G = out_size / OUT_C;        // 128

    const int* src = ei;
    const int* dst = ei + E;

    void *p_degi, *p_acc1, *p_acc2, *p_gsum, *p_gcnt, *p_g1h, *p_g2h;
    cudaGetSymbolAddress(&p_degi, g_degi);
    cudaGetSymbolAddress(&p_acc1, g_acc1);
    cudaGetSymbolAddress(&p_acc2, g_acc2);
    cudaGetSymbolAddress(&p_gsum, g_gsum);
    cudaGetSymbolAddress(&p_gcnt, g_gcnt);
    cudaGetSymbolAddress(&p_g1h, g_g1h);
    cudaGetSymbolAddress(&p_g2h, g_g2h);

    cudaMemsetAsync(p_degi, 0, (size_t)N * sizeof(int));
    cudaMemsetAsync(p_acc1, 0, (size_t)N * HID_C * sizeof(__half));
    cudaMemsetAsync(p_acc2, 0, (size_t)N * OUT_C * sizeof(__half));
    cudaMemsetAsync(p_gsum, 0, (size_t)G * OUT_C * sizeof(float));
    cudaMemsetAsync(p_gcnt, 0, (size_t)G * sizeof(float));

    deg_kernel <<<(E + 255) / 256, 256>>>(dst, E);
    scan_kernel<<<1, 1024>>>(N);                       // cursors + dinv
    fill_kernel<<<(E + 255) / 256, 256>>>(src, dst, E);

    // GEMM1: g1h = dinv * (x @ W1)
    {
        const int smem = (128 * 136 + 128 * (128 + 8)) * (int)sizeof(__half);
        cudaFuncSetAttribute(hgemm_kernel<128, false>,
                             cudaFuncAttributeMaxDynamicSharedMemorySize, smem);
        hgemm_kernel<128, false><<<(N + 127) / 128, 256, smem>>>(
            x, nullptr, W1, (__half*)p_g1h, N);
    }
    {   // scatter1: (E/8) groups of 16 lanes
        long long threads = ((long long)(E + 7) / 8) * 16;
        scatter1s_kernel<<<(int)((threads + 255) / 256), 256>>>(E);
    }

    // GEMM2: g2h = dinv * (relu(dinv*(acc1+g1h)+b1) @ W2)
    {
        const int smem = (128 * 136 + 128 * (64 + 8)) * (int)sizeof(__half);
        cudaFuncSetAttribute(hgemm_kernel<64, true>,
                             cudaFuncAttributeMaxDynamicSharedMemorySize, smem);
        hgemm_kernel<64, true><<<(N + 127) / 128, 256, smem>>>(
            nullptr, b1, W2, (__half*)p_g2h, N);
    }
    {   // scatter2: (E/8) groups of 8 lanes
        long long threads = ((long long)(E + 7) / 8) * 8;
        scatter2s_kernel<<<(int)((threads + 255) / 256), 256>>>(E);
    }

    pool_kernel<<<(N + 15) / 16, 256>>>(bat, b2, N);
    divide_kernel<<<(G * OUT_C + 255) / 256, 256>>>((float*)d_out, G);
}

// round 14
// speedup vs baseline: 1.0178x; 1.0178x over previous
#include <cuda_runtime.h>
#include <cuda_fp16.h>
#include <mma.h>
#include <cstddef>
#include <cstdint>

using namespace nvcuda;

#define N_NODES   50000
#define N_GRAPHS  128
#define IN_C      128
#define HID_C     128
#define OUT_C     64
#define E_MAX     700000

// ---------------- device scratch (no allocations allowed) ----------------
__device__ int    g_degi[N_NODES];
__device__ int    g_cur [N_NODES];                   // CSR fill cursors
__device__ int2   g_csr_sd[E_MAX];                   // (src,dst) sorted by dst
__device__ float  g_dinv[N_NODES];
__device__ __half g_g1h [(size_t)N_NODES * HID_C];   // fp16 messages L1
__device__ __half g_acc1[(size_t)N_NODES * HID_C];   // fp16 scatter accumulator L1
__device__ __half g_g2h [(size_t)N_NODES * OUT_C];   // fp16 messages L2
__device__ __half g_acc2[(size_t)N_NODES * OUT_C];   // fp16 scatter accumulator L2
__device__ float  g_gsum[N_GRAPHS * OUT_C];
__device__ float  g_gcnt[N_GRAPHS];

__device__ __forceinline__ void red_add_v4(float* p, float4 v) {
    asm volatile("red.global.add.v4.f32 [%0], {%1, %2, %3, %4};"
                 :: "l"(p), "f"(v.x), "f"(v.y), "f"(v.z), "f"(v.w)
                 : "memory");
}
// 8 halfs per op (16B) — sm_90+
__device__ __forceinline__ void red_add_v4h(__half* p, uint4 v) {
    asm volatile("red.global.add.noftz.v4.f16x2 [%0], {%1, %2, %3, %4};"
                 :: "l"(p), "r"(v.x), "r"(v.y), "r"(v.z), "r"(v.w)
                 : "memory");
}
__device__ __forceinline__ void h2x4_add(uint4& a, uint4 b) {
    __half2* pa = (__half2*)&a;
    const __half2* pb = (const __half2*)&b;
    pa[0] = __hadd2(pa[0], pb[0]);
    pa[1] = __hadd2(pa[1], pb[1]);
    pa[2] = __hadd2(pa[2], pb[2]);
    pa[3] = __hadd2(pa[3], pb[3]);
}
__device__ __forceinline__ uint4 f8_to_h8(float4 a, float4 b) {
    __half2 h0 = __floats2half2_rn(a.x, a.y);
    __half2 h1 = __floats2half2_rn(a.z, a.w);
    __half2 h2 = __floats2half2_rn(b.x, b.y);
    __half2 h3 = __floats2half2_rn(b.z, b.w);
    uint4 u;
    u.x = *reinterpret_cast<unsigned*>(&h0);
    u.y = *reinterpret_cast<unsigned*>(&h1);
    u.z = *reinterpret_cast<unsigned*>(&h2);
    u.w = *reinterpret_cast<unsigned*>(&h3);
    return u;
}

// ---------------- degree (by dst) ----------------
__global__ void deg_kernel(const int* __restrict__ dst, int E) {
    int e = blockIdx.x * blockDim.x + threadIdx.x;
    if (e < E) atomicAdd(&g_degi[dst[e]], 1);
}

// ---------------- exclusive scan -> cursors; dinv (1 block, 1024 thr) ----------------
__global__ void scan_kernel(int N) {
    __shared__ int ssum[1024];
    const int tid = threadIdx.x;
    const int C   = (N + 1023) / 1024;
    const int lo  = tid * C;
    const int hi  = min(lo + C, N);

    int s = 0;
    for (int i = lo; i < hi; i++) s += g_degi[i];
    ssum[tid] = s;
    __syncthreads();
    for (int off = 1; off < 1024; off <<= 1) {
        int v = (tid >= off) ? ssum[tid - off] : 0;
        __syncthreads();
        ssum[tid] += v;
        __syncthreads();
    }
    int running = ssum[tid] - s;   // exclusive base
    for (int i = lo; i < hi; i++) {
        g_cur[i] = running;
        int d = g_degi[i];
        g_dinv[i] = rsqrtf((float)(1 + d));   // +1 self-loop
        running += d;
    }
}

// ---------------- fill: dst-sorted (src,dst) pairs ----------------
__global__ void fill_kernel(const int* __restrict__ src,
                            const int* __restrict__ dst,
                            int E) {
    int e = blockIdx.x * blockDim.x + threadIdx.x;
    if (e < E) {
        int d = dst[e];
        int pos = atomicAdd(&g_cur[d], 1);
        g_csr_sd[pos] = make_int2(src[e], d);
    }
}

// ---------------- fp16 HMMA GEMM: C16 = dinv ⊙ (A[M,128] @ B[128,LD]) ----------------
template<int LD, bool FUSE_IN>
__global__ void __launch_bounds__(256)
hgemm_kernel(const float* __restrict__ A,
             const float* __restrict__ bias,
             const float* __restrict__ B,
             __half* __restrict__ C16, int M) {
    extern __shared__ __half sm[];
    constexpr int LDA = 136;
    constexpr int LDB = LD + 8;
    constexpr int NT  = LD / 32;
    __half* As = sm;
    __half* Bs = sm + 128 * LDA;

    const int tid    = threadIdx.x;
    const int wid    = tid >> 5;
    const int lane   = tid & 31;
    const int warp_m = wid >> 1;
    const int warp_n = wid & 1;
    const int row0   = blockIdx.x * 128;

#pragma unroll
    for (int it = 0; it < 8; it++) {
        int chunk = tid + it * 256;
        int r  = chunk >> 4;
        int c8 = chunk & 15;
        int grow = row0 + r;
        uint4 u;
        if (grow < M) {
            if (FUSE_IN) {
                float dv = g_dinv[grow];
                uint4 au = ((const uint4*)(g_acc1 + (size_t)grow * 128))[c8];
                uint4 gu = ((const uint4*)(g_g1h  + (size_t)grow * 128))[c8];
                float4 bv0 = *(const float4*)(bias + c8 * 8);
                float4 bv1 = *(const float4*)(bias + c8 * 8 + 4);
                const __half2* ah = (const __half2*)&au;
                const __half2* gh = (const __half2*)&gu;
                float4 lo, hi;
                float2 t0 = __half22float2(ah[0]), s0 = __half22float2(gh[0]);
                float2 t1 = __half22float2(ah[1]), s1 = __half22float2(gh[1]);
                float2 t2 = __half22float2(ah[2]), s2 = __half22float2(gh[2]);
                float2 t3 = __half22float2(ah[3]), s3 = __half22float2(gh[3]);
                lo.x = fmaxf(dv * (t0.x + s0.x) + bv0.x, 0.f);
                lo.y = fmaxf(dv * (t0.y + s0.y) + bv0.y, 0.f);
                lo.z = fmaxf(dv * (t1.x + s1.x) + bv0.z, 0.f);
                lo.w = fmaxf(dv * (t1.y + s1.y) + bv0.w, 0.f);
                hi.x = fmaxf(dv * (t2.x + s2.x) + bv1.x, 0.f);
                hi.y = fmaxf(dv * (t2.y + s2.y) + bv1.y, 0.f);
                hi.z = fmaxf(dv * (t3.x + s3.x) + bv1.z, 0.f);
                hi.w = fmaxf(dv * (t3.y + s3.y) + bv1.w, 0.f);
                u = f8_to_h8(lo, hi);
            } else {
                float4 lo = *(const float4*)(A + (size_t)grow * 128 + c8 * 8);
                float4 hi = *(const float4*)(A + (size_t)grow * 128 + c8 * 8 + 4);
                u = f8_to_h8(lo, hi);
            }
        } else {
            u = make_uint4(0, 0, 0, 0);
        }
        *(uint4*)(As + r * LDA + c8 * 8) = u;
    }
    constexpr int BCH = 128 * LD / 8 / 256;
#pragma unroll
    for (int it = 0; it < BCH; it++) {
        int chunk = tid + it * 256;
        int r  = chunk / (LD / 8);
        int c8 = chunk % (LD / 8);
        float4 lo = *(const float4*)(B + (size_t)r * LD + c8 * 8);
        float4 hi = *(const float4*)(B + (size_t)r * LD + c8 * 8 + 4);
        *(uint4*)(Bs + r * LDB + c8 * 8) = f8_to_h8(lo, hi);
    }
    __syncthreads();

    wmma::fragment<wmma::accumulator, 16, 16, 16, float> acc[2][NT];
#pragma unroll
    for (int i = 0; i < 2; i++)
#pragma unroll
        for (int nt = 0; nt < NT; nt++) wmma::fill_fragment(acc[i][nt], 0.f);

#pragma unroll
    for (int k = 0; k < 8; k++) {
        wmma::fragment<wmma::matrix_a, 16, 16, 16, __half, wmma::row_major> a0, a1;
        wmma::load_matrix_sync(a0, As + (warp_m * 32 +  0) * LDA + k * 16, LDA);
        wmma::load_matrix_sync(a1, As + (warp_m * 32 + 16) * LDA + k * 16, LDA);
#pragma unroll
        for (int nt = 0; nt < NT; nt++) {
            wmma::fragment<wmma::matrix_b, 16, 16, 16, __half, wmma::row_major> b;
            wmma::load_matrix_sync(b, Bs + (k * 16) * LDB + warp_n * (LD / 2) + nt * 16, LDB);
            wmma::mma_sync(acc[0][nt], a0, b, acc[0][nt]);
            wmma::mma_sync(acc[1][nt], a1, b, acc[1][nt]);
        }
    }
    __syncthreads();

    float* wbuf = (float*)(sm) + wid * 256;    // ldm=16 (16B multiple — WMMA contract)
#pragma unroll
    for (int i = 0; i < 2; i++) {
#pragma unroll
        for (int nt = 0; nt < NT; nt++) {
            wmma::store_matrix_sync(wbuf, acc[i][nt], 16, wmma::mem_row_major);
            __syncwarp();
            int r  = lane >> 1;
            int c8 = (lane & 1) * 8;
            int grow = row0 + warp_m * 32 + i * 16 + r;
            if (grow < M) {
                float d = g_dinv[grow];
                const float* p = wbuf + r * 16 + c8;
                float4 lo = make_float4(d * p[0], d * p[1], d * p[2], d * p[3]);
                float4 hi = make_float4(d * p[4], d * p[5], d * p[6], d * p[7]);
                int col = warp_n * (LD / 2) + nt * 16 + c8;
                *(uint4*)(C16 + (size_t)grow * LD + col) = f8_to_h8(lo, hi);
            }
            __syncwarp();
        }
    }
}

// ---------------- scatter 1: sorted runs of 8, BRANCHLESS segmented combine ----------------
// 16-lane group handles 8 consecutive dst-sorted edges; row = 128 halfs = 16 uint4.
__global__ void __launch_bounds__(256)
scatter1s_kernel(int E) {
    int t = blockIdx.x * blockDim.x + threadIdx.x;
    int grp  = t >> 4;
    int lane = t & 15;
    int e0 = grp * 8;
    if (e0 >= E) return;

    const uint4* base = (const uint4*)g_g1h;   // 16 uint4 per row
    int sd_s[8], sd_d[8];
#pragma unroll
    for (int j = 0; j < 8; j++) {
        int2 p = (e0 + j < E) ? g_csr_sd[e0 + j] : make_int2(0, -1);
        sd_s[j] = p.x;
        sd_d[j] = p.y;
    }
    uint4 v[8];
#pragma unroll
    for (int j = 0; j < 8; j++)
        v[j] = (sd_d[j] >= 0) ? base[(size_t)sd_s[j] * 16 + lane]
                              : make_uint4(0, 0, 0, 0);

    // suffix combine within run (predicated, no branches)
#pragma unroll
    for (int j = 6; j >= 0; j--)
        if (sd_d[j] == sd_d[j + 1]) h2x4_add(v[j], v[j + 1]);
    // flush at run heads (predicated RED)
#pragma unroll
    for (int j = 0; j < 8; j++) {
        bool head = (j == 0) || (sd_d[j] != sd_d[j - 1]);
        if (head && sd_d[j] >= 0)
            red_add_v4h(g_acc1 + (size_t)sd_d[j] * HID_C + lane * 8, v[j]);
    }
}

// ---------------- scatter 2: sorted runs of 8, branchless; row = 64 halfs = 8 uint4 ----------------
__global__ void __launch_bounds__(256)
scatter2s_kernel(int E) {
    int t = blockIdx.x * blockDim.x + threadIdx.x;
    int grp  = t >> 3;
    int lane = t & 7;
    int e0 = grp * 8;
    if (e0 >= E) return;

    const uint4* base = (const uint4*)g_g2h;   // 8 uint4 per row
    int sd_s[8], sd_d[8];
#pragma unroll
    for (int j = 0; j < 8; j++) {
        int2 p = (e0 + j < E) ? g_csr_sd[e0 + j] : make_int2(0, -1);
        sd_s[j] = p.x;
        sd_d[j] = p.y;
    }
    uint4 v[8];
#pragma unroll
    for (int j = 0; j < 8; j++)
        v[j] = (sd_d[j] >= 0) ? base[(size_t)sd_s[j] * 8 + lane]
                              : make_uint4(0, 0, 0, 0);

#pragma unroll
    for (int j = 6; j >= 0; j--)
        if (sd_d[j] == sd_d[j + 1]) h2x4_add(v[j], v[j + 1]);
#pragma unroll
    for (int j = 0; j < 8; j++) {
        bool head = (j == 0) || (sd_d[j] != sd_d[j - 1]);
        if (head && sd_d[j] >= 0)
            red_add_v4h(g_acc2 + (size_t)sd_d[j] * OUT_C + lane * 8, v[j]);
    }
}

// ---------------- pool: out2 = dinv*(acc2+g2h)+b2; RED into graph sums ----------------
__global__ void pool_kernel(const int* __restrict__ batch,
                            const float* __restrict__ b2,
                            int N) {
    int t = blockIdx.x * blockDim.x + threadIdx.x;
    int node = t >> 4;
    int lane = t & 15;
    if (node >= N) return;
    int b = batch[node];
    float dv = g_dinv[node];
    uint2 au = ((const uint2*)(g_acc2 + (size_t)node * OUT_C))[lane];
    uint2 gu = ((const uint2*)(g_g2h  + (size_t)node * OUT_C))[lane];
    __half2 ah0 = *reinterpret_cast<__half2*>(&au.x);
    __half2 ah1 = *reinterpret_cast<__half2*>(&au.y);
    __half2 gh0 = *reinterpret_cast<__half2*>(&gu.x);
    __half2 gh1 = *reinterpret_cast<__half2*>(&gu.y);
    float2 a0 = __half22float2(ah0), a1 = __half22float2(ah1);
    float2 g0 = __half22float2(gh0), g1 = __half22float2(gh1);
    float4 bv = *(const float4*)(b2 + lane * 4);
    float4 r;
    r.x = dv * (a0.x + g0.x) + bv.x;
    r.y = dv * (a0.y + g0.y) + bv.y;
    r.z = dv * (a1.x + g1.x) + bv.z;
    r.w = dv * (a1.y + g1.y) + bv.w;
    red_add_v4(g_gsum + b * OUT_C + lane * 4, r);
    if (lane == 0) atomicAdd(&g_gcnt[b], 1.0f);
}

__global__ void divide_kernel(float* __restrict__ out, int G) {
    int i = blockIdx.x * blockDim.x + threadIdx.x;
    if (i < G * OUT_C) {
        float c = g_gcnt[i / OUT_C];
        out[i] = g_gsum[i] / fmaxf(c, 1.0f);
    }
}

// ---------------- launch ----------------
extern "C" void kernel_launch(void* const* d_in, const int* in_sizes, int n_in,
                              void* d_out, int out_size) {
    const float* x   = (const float*)d_in[0];
    const float* W1  = (const float*)d_in[1];
    const float* b1  = (const float*)d_in[2];
    const float* W2  = (const float*)d_in[3];
    const float* b2  = (const float*)d_in[4];
    const int*   ei  = (const int*)d_in[5];   // int32
    const int*   bat = (const int*)d_in[6];

    const int N = in_sizes[0] / IN_C;      // 50000
    const int E = in_sizes[5] / 2;         // 625000
    const int G = out_size / OUT_C;        // 128

    const int* src = ei;
    const int* dst = ei + E;

    void *p_degi, *p_acc1, *p_acc2, *p_gsum, *p_gcnt, *p_g1h, *p_g2h;
    cudaGetSymbolAddress(&p_degi, g_degi);
    cudaGetSymbolAddress(&p_acc1, g_acc1);
    cudaGetSymbolAddress(&p_acc2, g_acc2);
    cudaGetSymbolAddress(&p_gsum, g_gsum);
    cudaGetSymbolAddress(&p_gcnt, g_gcnt);
    cudaGetSymbolAddress(&p_g1h, g_g1h);
    cudaGetSymbolAddress(&p_g2h, g_g2h);

    cudaMemsetAsync(p_degi, 0, (size_t)N * sizeof(int));
    cudaMemsetAsync(p_acc1, 0, (size_t)N * HID_C * sizeof(__half));
    cudaMemsetAsync(p_acc2, 0, (size_t)N * OUT_C * sizeof(__half));
    cudaMemsetAsync(p_gsum, 0, (size_t)G * OUT_C * sizeof(float));
    cudaMemsetAsync(p_gcnt, 0, (size_t)G * sizeof(float));

    deg_kernel <<<(E + 255) / 256, 256>>>(dst, E);
    scan_kernel<<<1, 1024>>>(N);                       // cursors + dinv
    fill_kernel<<<(E + 255) / 256, 256>>>(src, dst, E);

    // GEMM1: g1h = dinv * (x @ W1)
    {
        const int smem = (128 * 136 + 128 * (128 + 8)) * (int)sizeof(__half);
        cudaFuncSetAttribute(hgemm_kernel<128, false>,
                             cudaFuncAttributeMaxDynamicSharedMemorySize, smem);
        hgemm_kernel<128, false><<<(N + 127) / 128, 256, smem>>>(
            x, nullptr, W1, (__half*)p_g1h, N);
    }
    {   // scatter1: (E/8) groups of 16 lanes
        long long threads = ((long long)(E + 7) / 8) * 16;
        scatter1s_kernel<<<(int)((threads + 255) / 256), 256>>>(E);
    }

    // GEMM2: g2h = dinv * (relu(dinv*(acc1+g1h)+b1) @ W2)
    {
        const int smem = (128 * 136 + 128 * (64 + 8)) * (int)sizeof(__half);
        cudaFuncSetAttribute(hgemm_kernel<64, true>,
                             cudaFuncAttributeMaxDynamicSharedMemorySize, smem);
        hgemm_kernel<64, true><<<(N + 127) / 128, 256, smem>>>(
            nullptr, b1, W2, (__half*)p_g2h, N);
    }
    {   // scatter2: (E/8) groups of 8 lanes
        long long threads = ((long long)(E + 7) / 8) * 8;
        scatter2s_kernel<<<(int)((threads + 255) / 256), 256>>>(E);
    }

    pool_kernel<<<(N + 15) / 16, 256>>>(bat, b2, N);
    divide_kernel<<<(G * OUT_C + 255) / 256, 256>>>((float*)d_out, G);
}

// round 15
// speedup vs baseline: 1.5816x; 1.5539x over previous
#include <cuda_runtime.h>
#include <cuda_fp16.h>
#include <mma.h>
#include <cstddef>
#include <cstdint>

using namespace nvcuda;

#define N_NODES   50000
#define N_GRAPHS  128
#define IN_C      128
#define HID_C     128
#define OUT_C     64

// ---------------- device scratch (no allocations allowed) ----------------
__device__ int    g_degi[N_NODES];
__device__ __half g_g1h [(size_t)N_NODES * HID_C];   // fp16 messages L1
__device__ __half g_acc1[(size_t)N_NODES * HID_C];   // fp16 scatter accumulator L1
__device__ __half g_g2h [(size_t)N_NODES * OUT_C];   // fp16 messages L2
__device__ __half g_acc2[(size_t)N_NODES * OUT_C];   // fp16 scatter accumulator L2
__device__ float  g_gsum[N_GRAPHS * OUT_C];
__device__ float  g_gcnt[N_GRAPHS];

__device__ __forceinline__ float node_dinv(int i) {
    return rsqrtf((float)(1 + g_degi[i]));   // +1 self-loop
}
__device__ __forceinline__ void red_add_v4(float* p, float4 v) {
    asm volatile("red.global.add.v4.f32 [%0], {%1, %2, %3, %4};"
                 :: "l"(p), "f"(v.x), "f"(v.y), "f"(v.z), "f"(v.w)
                 : "memory");
}
// 8 halfs per op (16B) — sm_90+
__device__ __forceinline__ void red_add_v4h(__half* p, uint4 v) {
    asm volatile("red.global.add.noftz.v4.f16x2 [%0], {%1, %2, %3, %4};"
                 :: "l"(p), "r"(v.x), "r"(v.y), "r"(v.z), "r"(v.w)
                 : "memory");
}
__device__ __forceinline__ uint4 f8_to_h8(float4 a, float4 b) {
    __half2 h0 = __floats2half2_rn(a.x, a.y);
    __half2 h1 = __floats2half2_rn(a.z, a.w);
    __half2 h2 = __floats2half2_rn(b.x, b.y);
    __half2 h3 = __floats2half2_rn(b.z, b.w);
    uint4 u;
    u.x = *reinterpret_cast<unsigned*>(&h0);
    u.y = *reinterpret_cast<unsigned*>(&h1);
    u.z = *reinterpret_cast<unsigned*>(&h2);
    u.w = *reinterpret_cast<unsigned*>(&h3);
    return u;
}

// ---------------- fused zero-init of all accumulator arrays ----------------
// sizes in uint4 units
#define Z_ACC1 ((N_NODES * HID_C * 2) / 16)       // 819200? no: 50000*128*2/16 = 800000
#define Z_ACC2 ((N_NODES * OUT_C * 2) / 16)       // 400000
#define Z_DEGI ((N_NODES * 4) / 16)               // 12500
#define Z_GSUM ((N_GRAPHS * OUT_C * 4) / 16)      // 2048
#define Z_GCNT ((N_GRAPHS * 4) / 16)              // 32
#define Z_TOTAL (Z_ACC1 + Z_ACC2 + Z_DEGI + Z_GSUM + Z_GCNT)

__global__ void init_kernel() {
    uint4 z = make_uint4(0, 0, 0, 0);
    for (int i = blockIdx.x * blockDim.x + threadIdx.x; i < Z_TOTAL;
         i += gridDim.x * blockDim.x) {
        if (i < Z_ACC1) {
            ((uint4*)g_acc1)[i] = z;
        } else if (i < Z_ACC1 + Z_ACC2) {
            ((uint4*)g_acc2)[i - Z_ACC1] = z;
        } else if (i < Z_ACC1 + Z_ACC2 + Z_DEGI) {
            ((uint4*)g_degi)[i - Z_ACC1 - Z_ACC2] = z;
        } else if (i < Z_ACC1 + Z_ACC2 + Z_DEGI + Z_GSUM) {
            ((uint4*)g_gsum)[i - Z_ACC1 - Z_ACC2 - Z_DEGI] = z;
        } else {
            ((uint4*)g_gcnt)[i - Z_ACC1 - Z_ACC2 - Z_DEGI - Z_GSUM] = z;
        }
    }
}

// ---------------- degree (by dst) ----------------
__global__ void deg_kernel(const int* __restrict__ dst, int E) {
    int e = blockIdx.x * blockDim.x + threadIdx.x;
    if (e < E) atomicAdd(&g_degi[dst[e]], 1);
}

// ---------------- fp16 HMMA GEMM, BM=64: C16 = dinv ⊙ (A[M,128] @ B[128,LD]) ----------------
// 256 threads = 8 warps as 4(m) x 2(n); warp covers 16 rows x LD/2 cols.
// K=128 staged in smem (8 k16 steps). A,B converted fp32->fp16 on load.
// FUSE_IN: A row = relu(dinv*(acc1+g1h)+bias)  (layer-2 input, fp16 sources).
template<int LD, bool FUSE_IN>
__global__ void __launch_bounds__(256)
hgemm_kernel(const float* __restrict__ A,
             const float* __restrict__ bias,
             const float* __restrict__ B,
             __half* __restrict__ C16, int M) {
    extern __shared__ __half sm[];
    constexpr int LDA = 136;          // 128 + 8 pad
    constexpr int LDB = LD + 8;
    constexpr int NT  = LD / 32;      // 16-wide n-tiles per warp
    __half* As = sm;                  // [64][136]
    __half* Bs = sm + 64 * LDA;       // [128][LDB]

    const int tid    = threadIdx.x;
    const int wid    = tid >> 5;
    const int lane   = tid & 31;
    const int warp_m = wid >> 1;      // 0..3 -> rows warp_m*16
    const int warp_n = wid & 1;       // 0..1 -> cols warp_n*(LD/2)
    const int row0   = blockIdx.x * 64;

    // ---- stage A: 64*128 halfs = 1024 chunks of 8; 4 iters ----
#pragma unroll
    for (int it = 0; it < 4; it++) {
        int chunk = tid + it * 256;
        int r  = chunk >> 4;
        int c8 = chunk & 15;
        int grow = row0 + r;
        uint4 u;
        if (grow < M) {
            if (FUSE_IN) {
                float dv = node_dinv(grow);
                uint4 au = ((const uint4*)(g_acc1 + (size_t)grow * 128))[c8];
                uint4 gu = ((const uint4*)(g_g1h  + (size_t)grow * 128))[c8];
                float4 bv0 = *(const float4*)(bias + c8 * 8);
                float4 bv1 = *(const float4*)(bias + c8 * 8 + 4);
                const __half2* ah = (const __half2*)&au;
                const __half2* gh = (const __half2*)&gu;
                float4 lo, hi;
                float2 t0 = __half22float2(ah[0]), s0 = __half22float2(gh[0]);
                float2 t1 = __half22float2(ah[1]), s1 = __half22float2(gh[1]);
                float2 t2 = __half22float2(ah[2]), s2 = __half22float2(gh[2]);
                float2 t3 = __half22float2(ah[3]), s3 = __half22float2(gh[3]);
                lo.x = fmaxf(dv * (t0.x + s0.x) + bv0.x, 0.f);
                lo.y = fmaxf(dv * (t0.y + s0.y) + bv0.y, 0.f);
                lo.z = fmaxf(dv * (t1.x + s1.x) + bv0.z, 0.f);
                lo.w = fmaxf(dv * (t1.y + s1.y) + bv0.w, 0.f);
                hi.x = fmaxf(dv * (t2.x + s2.x) + bv1.x, 0.f);
                hi.y = fmaxf(dv * (t2.y + s2.y) + bv1.y, 0.f);
                hi.z = fmaxf(dv * (t3.x + s3.x) + bv1.z, 0.f);
                hi.w = fmaxf(dv * (t3.y + s3.y) + bv1.w, 0.f);
                u = f8_to_h8(lo, hi);
            } else {
                float4 lo = *(const float4*)(A + (size_t)grow * 128 + c8 * 8);
                float4 hi = *(const float4*)(A + (size_t)grow * 128 + c8 * 8 + 4);
                u = f8_to_h8(lo, hi);
            }
        } else {
            u = make_uint4(0, 0, 0, 0);
        }
        *(uint4*)(As + r * LDA + c8 * 8) = u;
    }
    // ---- stage B: 128*LD halfs ----
    constexpr int BCH = 128 * LD / 8 / 256;   // 8 (LD=128) or 4 (LD=64)
#pragma unroll
    for (int it = 0; it < BCH; it++) {
        int chunk = tid + it * 256;
        int r  = chunk / (LD / 8);
        int c8 = chunk % (LD / 8);
        float4 lo = *(const float4*)(B + (size_t)r * LD + c8 * 8);
        float4 hi = *(const float4*)(B + (size_t)r * LD + c8 * 8 + 4);
        *(uint4*)(Bs + r * LDB + c8 * 8) = f8_to_h8(lo, hi);
    }
    __syncthreads();

    // ---- MMA: 8 k-steps, 1 m-frag x NT n-frags per warp ----
    wmma::fragment<wmma::accumulator, 16, 16, 16, float> acc[NT];
#pragma unroll
    for (int nt = 0; nt < NT; nt++) wmma::fill_fragment(acc[nt], 0.f);

#pragma unroll
    for (int k = 0; k < 8; k++) {
        wmma::fragment<wmma::matrix_a, 16, 16, 16, __half, wmma::row_major> a0;
        wmma::load_matrix_sync(a0, As + (warp_m * 16) * LDA + k * 16, LDA);
#pragma unroll
        for (int nt = 0; nt < NT; nt++) {
            wmma::fragment<wmma::matrix_b, 16, 16, 16, __half, wmma::row_major> b;
            wmma::load_matrix_sync(b, Bs + (k * 16) * LDB + warp_n * (LD / 2) + nt * 16, LDB);
            wmma::mma_sync(acc[nt], a0, b, acc[nt]);
        }
    }
    __syncthreads();

    // ---- epilogue: per-warp staging (ldm=16 — WMMA contract), dinv, fp16 store ----
    float* wbuf = (float*)(sm) + wid * 256;    // 16x16 floats per warp
#pragma unroll
    for (int nt = 0; nt < NT; nt++) {
        wmma::store_matrix_sync(wbuf, acc[nt], 16, wmma::mem_row_major);
        __syncwarp();
        int r  = lane >> 1;
        int c8 = (lane & 1) * 8;
        int grow = row0 + warp_m * 16 + r;
        if (grow < M) {
            float d = node_dinv(grow);
            const float* p = wbuf + r * 16 + c8;
            float4 lo = make_float4(d * p[0], d * p[1], d * p[2], d * p[3]);
            float4 hi = make_float4(d * p[4], d * p[5], d * p[6], d * p[7]);
            int col = warp_n * (LD / 2) + nt * 16 + c8;
            *(uint4*)(C16 + (size_t)grow * LD + col) = f8_to_h8(lo, hi);
        }
        __syncwarp();
    }
}

// ---------------- scatter layer 1: acc1[dst] += g1h[src] (128 halfs/edge, 16 lanes) ----------------
__global__ void scatter1_kernel(const int* __restrict__ src,
                                const int* __restrict__ dst,
                                int E) {
    int t = blockIdx.x * blockDim.x + threadIdx.x;
    int e = t >> 4;
    int lane = t & 15;
    if (e >= E) return;
    int s = src[e];
    int d = dst[e];
    uint4 v = ((const uint4*)(g_g1h + (size_t)s * HID_C))[lane];  // 8 halfs
    red_add_v4h(g_acc1 + (size_t)d * HID_C + lane * 8, v);
}

// ---------------- scatter layer 2: acc2[dst] += g2h[src] (64 halfs/edge, 8 lanes) ----------------
__global__ void scatter2_kernel(const int* __restrict__ src,
                                const int* __restrict__ dst,
                                int E) {
    int t = blockIdx.x * blockDim.x + threadIdx.x;
    int e = t >> 3;
    int lane = t & 7;
    if (e >= E) return;
    int s = src[e];
    int d = dst[e];
    uint4 v = ((const uint4*)(g_g2h + (size_t)s * OUT_C))[lane];  // 8 halfs
    red_add_v4h(g_acc2 + (size_t)d * OUT_C + lane * 8, v);
}

// ---------------- pool: out2 = dinv*(acc2+g2h)+b2; RED into graph sums ----------------
__global__ void pool_kernel(const int* __restrict__ batch,
                            const float* __restrict__ b2,
                            int N) {
    int t = blockIdx.x * blockDim.x + threadIdx.x;
    int node = t >> 4;
    int lane = t & 15;
    if (node >= N) return;
    int b = batch[node];
    float dv = node_dinv(node);
    uint2 au = ((const uint2*)(g_acc2 + (size_t)node * OUT_C))[lane];
    uint2 gu = ((const uint2*)(g_g2h  + (size_t)node * OUT_C))[lane];
    __half2 ah0 = *reinterpret_cast<__half2*>(&au.x);
    __half2 ah1 = *reinterpret_cast<__half2*>(&au.y);
    __half2 gh0 = *reinterpret_cast<__half2*>(&gu.x);
    __half2 gh1 = *reinterpret_cast<__half2*>(&gu.y);
    float2 a0 = __half22float2(ah0), a1 = __half22float2(ah1);
    float2 g0 = __half22float2(gh0), g1 = __half22float2(gh1);
    float4 bv = *(const float4*)(b2 + lane * 4);
    float4 r;
    r.x = dv * (a0.x + g0.x) + bv.x;
    r.y = dv * (a0.y + g0.y) + bv.y;
    r.z = dv * (a1.x + g1.x) + bv.z;
    r.w = dv * (a1.y + g1.y) + bv.w;
    red_add_v4(g_gsum + b * OUT_C + lane * 4, r);
    if (lane == 0) atomicAdd(&g_gcnt[b], 1.0f);
}

__global__ void divide_kernel(float* __restrict__ out, int G) {
    int i = blockIdx.x * blockDim.x + threadIdx.x;
    if (i < G * OUT_C) {
        float c = g_gcnt[i / OUT_C];
        out[i] = g_gsum[i] / fmaxf(c, 1.0f);
    }
}

// ---------------- launch ----------------
extern "C" void kernel_launch(void* const* d_in, const int* in_sizes, int n_in,
                              void* d_out, int out_size) {
    const float* x   = (const float*)d_in[0];
    const float* W1  = (const float*)d_in[1];
    const float* b1  = (const float*)d_in[2];
    const float* W2  = (const float*)d_in[3];
    const float* b2  = (const float*)d_in[4];
    const int*   ei  = (const int*)d_in[5];   // int32
    const int*   bat = (const int*)d_in[6];

    const int N = in_sizes[0] / IN_C;      // 50000
    const int E = in_sizes[5] / 2;         // 625000
    const int G = out_size / OUT_C;        // 128

    const int* src = ei;
    const int* dst = ei + E;

    void *p_g1h, *p_g2h;
    cudaGetSymbolAddress(&p_g1h, g_g1h);
    cudaGetSymbolAddress(&p_g2h, g_g2h);

    // fused zero-init (replaces 5 memsets)
    init_kernel<<<592, 256>>>();   // 148 SMs * 4
    deg_kernel <<<(E + 255) / 256, 256>>>(dst, E);

    // GEMM1: g1h = dinv * (x @ W1)
    {
        const int smem = (64 * 136 + 128 * (128 + 8)) * (int)sizeof(__half);
        cudaFuncSetAttribute(hgemm_kernel<128, false>,
                             cudaFuncAttributeMaxDynamicSharedMemorySize, smem);
        hgemm_kernel<128, false><<<(N + 63) / 64, 256, smem>>>(
            x, nullptr, W1, (__half*)p_g1h, N);
    }
    scatter1_kernel<<<((size_t)E * 16 + 255) / 256, 256>>>(src, dst, E);

    // GEMM2: g2h = dinv * (relu(dinv*(acc1+g1h)+b1) @ W2)
    {
        const int smem = (64 * 136 + 128 * (64 + 8)) * (int)sizeof(__half);
        cudaFuncSetAttribute(hgemm_kernel<64, true>,
                             cudaFuncAttributeMaxDynamicSharedMemorySize, smem);
        hgemm_kernel<64, true><<<(N + 63) / 64, 256, smem>>>(
            nullptr, b1, W2, (__half*)p_g2h, N);
    }
    scatter2_kernel<<<((size_t)E * 8 + 255) / 256, 256>>>(src, dst, E);

    pool_kernel<<<(N + 15) / 16, 256>>>(bat, b2, N);
    divide_kernel<<<(G * OUT_C + 255) / 256, 256>>>((float*)d_out, G);
}